// round 7
// baseline (speedup 1.0000x reference)
#include <cuda_runtime.h>
#include <cuda_fp16.h>

// MultiScaleDeformableAttention, GB300 sm_103a.
// B=4, Q=21760, NH=8, DH=32, NL=4, NP=4, S=21760
// levels (square): 128,64,32,16 ; element starts: 0,16384,20480,21504
//
// Kernel 1: value f32 [b,s,h,d] -> fp16 scratch [b,h,s,d] (44.6MB, L2-resident).
// Kernel 2: one warp per (b,q,h). A bilinear corner pair (x, x+1) for all 32
//   channels is 128B contiguous in the fp16 layout. Lanes 0-15 read the TOP
//   row, lanes 16-31 the BOTTOM row (compile-time +Wl*64B per level): ONE
//   LDG.64 per sample fetches all 4 corners x 32 channels (16 LDG/warp).
//   Per sample, 3 shfls (src lane = s | corner<<4) + 1 row-select deliver the
//   offset and pre-folded f32 corner weight; 2 packed f32x2 FMAs accumulate.
//   NOTE: offv holds ONLY the in-level cell offset; the level base LSe[l]*64
//   lives in base_l (folds into the LDG immediate). R5 double-added it.

#define FULLMASK 0xffffffffu

constexpr int kQ = 21760;
constexpr int kS = 21760;

__device__ __align__(256) __half g_vhalf[4 * 8 * 21760 * 32];   // [b,h,s,d]

// ---------------------------------------------------------------------------
// Pre-pass: f32 [b,s,h,d] -> fp16 [b,h,s,d]
__global__ __launch_bounds__(256)
void convert_kernel(const float* __restrict__ value)
{
    const int warp = (blockIdx.x * 256 + threadIdx.x) >> 5;  // b*(S/2) + s/2
    const int lane = threadIdx.x & 31;
    const int b = warp / (kS / 2);
    const int s = (warp % (kS / 2)) * 2 + (lane >> 4);
    const int c = lane & 15;                                 // half2 index in d

    const float2* src =
        reinterpret_cast<const float2*>(value) + (size_t)(b * kS + s) * 128;
    __half* dstb = g_vhalf + (size_t)b * 8 * kS * 32;

#pragma unroll
    for (int h = 0; h < 8; ++h) {
        const float2 v = __ldg(src + h * 16 + c);
        const __half2 hv = __floats2half2_rn(v.x, v.y);
        *reinterpret_cast<__half2*>(dstb + ((size_t)h * kS + s) * 32 + 2 * c) = hv;
    }
}

// ---------------------------------------------------------------------------
__global__ __launch_bounds__(256)
void msda_kernel(const float* __restrict__ loc,
                 const float* __restrict__ attw,
                 float* __restrict__ out)
{
    const int warp = (blockIdx.x * 256 + threadIdx.x) >> 5;   // (b*Q+q)*8+h
    const int lane = threadIdx.x & 31;
    const int h  = warp & 7;
    const int bq = warp >> 3;
    const int b  = bq / kQ;

    // ---- precompute: lanes j and j+16 both do sample j; fold wx0 vs wx1 ----
    const int j = lane & 15;
    const float2 lc = __ldg(reinterpret_cast<const float2*>(loc) + (size_t)warp * 16 + j);
    const float  aw = __ldg(attw + (size_t)warp * 16 + j);

    const int   lvl = j >> 2;
    const int   Wl  = 128 >> lvl;
    const float Wf  = (float)Wl;

    const float x  = lc.x * Wf - 0.5f;
    const float y  = lc.y * Wf - 0.5f;
    const float xf = floorf(x);
    const float yf = floorf(y);
    const int   x0 = (int)xf;            // in [-1, Wl-1]
    const int   y0 = (int)yf;
    const float fx = x - xf;
    const float fy = y - yf;

    // Clamp base cell to [0, Wl-2]; remap weights so clamped-away corners get 0.
    float wx0 = 1.0f - fx, wx1 = fx;
    int   xb  = x0;
    if (x0 < 0)      { xb = 0;      wx0 = fx;   wx1 = 0.0f; }
    if (x0 > Wl - 2) { xb = Wl - 2; wx0 = 0.0f; wx1 = 1.0f - fx; }
    float wy0 = 1.0f - fy, wy1 = fy;
    int   yb  = y0;
    if (y0 < 0)      { yb = 0;      wy0 = fy;   wy1 = 0.0f; }
    if (y0 > Wl - 2) { yb = Wl - 2; wy0 = 0.0f; wy1 = 1.0f - fy; }

    const float xw = (lane & 16) ? wx1 : wx0;     // low half: LEFT corner
    const float Av = wy0 * aw * xw;               // top-row corner weight
    const float Bv = wy1 * aw * xw;               // bottom-row corner weight

    // In-level cell byte offset ONLY (level base added in base_l below).
    const int offv = (yb * Wl + xb) * 64;

    // ---- main-loop lane roles ----------------------------------------------
    // row = lane>>4 (0 top, 1 bottom); corner = (lane>>3)&1; chan-quad = lane&7
    const bool top  = lane < 16;
    const int  csrc = (lane & 8) << 1;            // corner -> +16 shfl source
    const int  rowsel = lane >> 4;                // 0 / 1

    const char* plane = reinterpret_cast<const char*>(
        g_vhalf + (size_t)(b * 8 + h) * kS * 32) + (lane & 15) * 8;
    const int rowoff0 = rowsel * 8192;            // row * 128 * 64B (level 0)

    const int LSe[4] = {0, 16384, 20480, 21504};

    unsigned long long a01 = 0ull, a23 = 0ull;    // f32x2 accumulators

#pragma unroll
    for (int l = 0; l < 4; ++l) {
        const char* base_l = plane + LSe[l] * 64 + (rowoff0 >> l);
#pragma unroll
        for (int p = 0; p < 4; ++p) {
            const int s   = l * 4 + p;
            const int src = s | csrc;

            const int   o  = __shfl_sync(FULLMASK, offv, src);
            const float wa = __shfl_sync(FULLMASK, Av,   src);
            const float wb = __shfl_sync(FULLMASK, Bv,   src);
            const float w  = top ? wa : wb;

            const uint2 v = __ldg(reinterpret_cast<const uint2*>(base_l + o));
            const float2 f01 = __half22float2(*reinterpret_cast<const __half2*>(&v.x));
            const float2 f23 = __half22float2(*reinterpret_cast<const __half2*>(&v.y));

            unsigned long long w2, u01, u23;
            asm("mov.b64 %0, {%1, %1};" : "=l"(w2) : "f"(w));
            asm("mov.b64 %0, {%1, %2};" : "=l"(u01) : "f"(f01.x), "f"(f01.y));
            asm("mov.b64 %0, {%1, %2};" : "=l"(u23) : "f"(f23.x), "f"(f23.y));
            asm("fma.rn.f32x2 %0, %1, %2, %0;" : "+l"(a01) : "l"(u01), "l"(w2));
            asm("fma.rn.f32x2 %0, %1, %2, %0;" : "+l"(a23) : "l"(u23), "l"(w2));
        }
    }

    // ---- reduce across corner (xor 8) and row (xor 16) groups --------------
    float r0, r1, r2, r3;
    asm("mov.b64 {%0, %1}, %2;" : "=f"(r0), "=f"(r1) : "l"(a01));
    asm("mov.b64 {%0, %1}, %2;" : "=f"(r2), "=f"(r3) : "l"(a23));

#pragma unroll
    for (int m = 8; m <= 16; m <<= 1) {
        r0 += __shfl_xor_sync(FULLMASK, r0, m);
        r1 += __shfl_xor_sync(FULLMASK, r1, m);
        r2 += __shfl_xor_sync(FULLMASK, r2, m);
        r3 += __shfl_xor_sync(FULLMASK, r3, m);
    }

    if (lane < 8) {
        // lane c holds channels 4c..4c+3 ; 8 lanes x float4 = 128B coalesced
        float4 o4 = make_float4(r0, r1, r2, r3);
        *reinterpret_cast<float4*>(out + (size_t)bq * 256 + h * 32 + lane * 4) = o4;
    }
}

extern "C" void kernel_launch(void* const* d_in, const int* in_sizes, int n_in,
                              void* d_out, int out_size)
{
    const float* value = (const float*)d_in[0];
    const float* loc   = (const float*)d_in[3];
    const float* attw  = (const float*)d_in[4];
    float* out = (float*)d_out;

    convert_kernel<<<43520 / 8, 256>>>(value);           // 4*(S/2) warps
    msda_kernel<<<696320 / 8, 256>>>(loc, attw, out);    // B*Q*NH warps
}